// round 1
// baseline (speedup 1.0000x reference)
#include <cuda_runtime.h>
#include <math.h>

#define Bb 16
#define Ss 512
#define Tt 512
#define Dd 512
#define Rr 8
#define NEG_BIG (-1e10f)

// scratch (device globals; no allocation allowed)
__device__ float g_wn[Rr * Dd];            // normalized w
__device__ float g_src_wt[Bb * Rr * Ss];   // [b,r,s]
__device__ float g_tar_wt[Bb * Rr * Tt];   // [b,r,t]
__device__ float g_c[Bb * Rr * Ss];        // softmax-weighted sum over t

// ---------------------------------------------------------------------------
// Kernel 1: row-L2-normalize w  (1 block, 8 warps, warp r handles row r)
// ---------------------------------------------------------------------------
__global__ void k_norm(const float* __restrict__ w) {
    int warp = threadIdx.x >> 5;
    int lane = threadIdx.x & 31;
    if (warp >= Rr) return;
    const float4* row = (const float4*)(w + warp * Dd);
    float4 x[4];
    float ss = 0.f;
#pragma unroll
    for (int k = 0; k < 4; k++) {
        x[k] = row[lane + 32 * k];
        ss += x[k].x * x[k].x + x[k].y * x[k].y + x[k].z * x[k].z + x[k].w * x[k].w;
    }
#pragma unroll
    for (int off = 16; off; off >>= 1)
        ss += __shfl_xor_sync(0xffffffffu, ss, off);
    float n = sqrtf(ss);
    float sc = 1.0f / fmaxf(n, 1e-12f);
    float4* outp = (float4*)(g_wn + warp * Dd);
#pragma unroll
    for (int k = 0; k < 4; k++) {
        float4 y;
        y.x = x[k].x * sc; y.y = x[k].y * sc; y.z = x[k].z * sc; y.w = x[k].w * sc;
        outp[lane + 32 * k] = y;
    }
}

// ---------------------------------------------------------------------------
// Kernel 2: src_wt[b,r,s] = src_emb[b,s,:]·wn[r,:], same for tar.
// One warp per row. 8 warps/block, 2048 blocks covers B*S + B*T = 16384 rows.
// ---------------------------------------------------------------------------
__global__ __launch_bounds__(256) void k_dots(const float* __restrict__ src,
                                              const float* __restrict__ tar) {
    __shared__ float4 wn_s[Rr * Dd / 4];  // 16 KB
    for (int i = threadIdx.x; i < Rr * Dd / 4; i += 256)
        wn_s[i] = ((const float4*)g_wn)[i];
    __syncthreads();

    int warp = threadIdx.x >> 5;
    int lane = threadIdx.x & 31;
    int gid = blockIdx.x * 8 + warp;

    const float4* row4;
    if (gid < Bb * Ss) row4 = (const float4*)(src + (size_t)gid * Dd);
    else               row4 = (const float4*)(tar + (size_t)(gid - Bb * Ss) * Dd);

    float acc[Rr];
#pragma unroll
    for (int r = 0; r < Rr; r++) acc[r] = 0.f;

#pragma unroll
    for (int k = 0; k < 4; k++) {
        float4 x = row4[lane + 32 * k];
#pragma unroll
        for (int r = 0; r < Rr; r++) {
            float4 wv = wn_s[r * 128 + lane + 32 * k];
            acc[r] = fmaf(x.x, wv.x, acc[r]);
            acc[r] = fmaf(x.y, wv.y, acc[r]);
            acc[r] = fmaf(x.z, wv.z, acc[r]);
            acc[r] = fmaf(x.w, wv.w, acc[r]);
        }
    }
#pragma unroll
    for (int off = 16; off; off >>= 1) {
#pragma unroll
        for (int r = 0; r < Rr; r++)
            acc[r] += __shfl_xor_sync(0xffffffffu, acc[r], off);
    }
    if (lane == 0) {
        float* dst;
        if (gid < Bb * Ss) {
            int b = gid / Ss, s = gid % Ss;
            dst = g_src_wt + (size_t)b * Rr * Ss + s;
        } else {
            int g2 = gid - Bb * Ss;
            int b = g2 / Tt, t = g2 % Tt;
            dst = g_tar_wt + (size_t)b * Rr * Tt + t;
        }
#pragma unroll
        for (int r = 0; r < Rr; r++) dst[r * Ss] = acc[r];  // S == T
    }
}

// ---------------------------------------------------------------------------
// Kernel 3: c[b,r,s] = sum_t softmax_t( a_s*v_t + (1 - sm_s*tm_t)*NEG_BIG ) * v_t
// grid = B*R blocks, 512 threads (one per s). Two-pass stable softmax.
// ---------------------------------------------------------------------------
__global__ __launch_bounds__(512) void k_attn(const float* __restrict__ src_mask,
                                              const float* __restrict__ tar_mask) {
    __shared__ float4 v_s[Tt / 4];
    __shared__ float4 tm_s[Tt / 4];
    int b = blockIdx.x / Rr;
    int r = blockIdx.x % Rr;
    int s = threadIdx.x;

    if (s < 128)            v_s[s]        = ((const float4*)(g_tar_wt + ((size_t)b * Rr + r) * Tt))[s];
    else if (s < 256)       tm_s[s - 128] = ((const float4*)(tar_mask + (size_t)b * Tt))[s - 128];
    __syncthreads();

    float a  = g_src_wt[((size_t)b * Rr + r) * Ss + s];
    float sm = src_mask[(size_t)b * Ss + s];

    // x_t = a*v_t + mt_t,  mt_t = fma(sm*tm_t, 1e10, -1e10)  (exactly 0 when product==1)
    float m = -3.4e38f;
#pragma unroll 4
    for (int t4 = 0; t4 < Tt / 4; t4++) {
        float4 v = v_s[t4], tm = tm_s[t4];
        float x0 = fmaf(a, v.x, fmaf(sm * tm.x, 1e10f, NEG_BIG));
        float x1 = fmaf(a, v.y, fmaf(sm * tm.y, 1e10f, NEG_BIG));
        float x2 = fmaf(a, v.z, fmaf(sm * tm.z, 1e10f, NEG_BIG));
        float x3 = fmaf(a, v.w, fmaf(sm * tm.w, 1e10f, NEG_BIG));
        m = fmaxf(m, fmaxf(fmaxf(x0, x1), fmaxf(x2, x3)));
    }
    float sum = 0.f, acc = 0.f;
#pragma unroll 4
    for (int t4 = 0; t4 < Tt / 4; t4++) {
        float4 v = v_s[t4], tm = tm_s[t4];
        float x0 = fmaf(a, v.x, fmaf(sm * tm.x, 1e10f, NEG_BIG));
        float x1 = fmaf(a, v.y, fmaf(sm * tm.y, 1e10f, NEG_BIG));
        float x2 = fmaf(a, v.z, fmaf(sm * tm.z, 1e10f, NEG_BIG));
        float x3 = fmaf(a, v.w, fmaf(sm * tm.w, 1e10f, NEG_BIG));
        float e0 = __expf(x0 - m);
        float e1 = __expf(x1 - m);
        float e2 = __expf(x2 - m);
        float e3 = __expf(x3 - m);
        sum += e0 + e1 + e2 + e3;
        acc = fmaf(e0, v.x, acc);
        acc = fmaf(e1, v.y, acc);
        acc = fmaf(e2, v.z, acc);
        acc = fmaf(e3, v.w, acc);
    }
    g_c[((size_t)b * Rr + r) * Ss + s] = acc / sum;
}

// ---------------------------------------------------------------------------
// Kernel 4: out[b,s,d] = sum_r c[b,r,s] * wn[r,d]
// grid = B * (S/64) = 128 blocks, 256 threads. Thread owns a fixed d-float4,
// wn held in registers, iterate over 64 s values (2 per pass across the block).
// ---------------------------------------------------------------------------
__global__ __launch_bounds__(256) void k_out(float* __restrict__ out) {
    __shared__ float c_s[64 * Rr];  // [j][r]
    int b  = blockIdx.x >> 3;
    int s0 = (blockIdx.x & 7) * 64;
    int tid = threadIdx.x;

    for (int i = tid; i < 64 * Rr; i += 256) {
        int j = i >> 3, r = i & 7;
        c_s[i] = g_c[((size_t)b * Rr + r) * Ss + s0 + j];
    }
    __syncthreads();

    int d4 = tid & 127;
    float4 wv[Rr];
#pragma unroll
    for (int r = 0; r < Rr; r++) wv[r] = ((const float4*)g_wn)[r * 128 + d4];

    float4* out4 = (float4*)out;
    for (int j = (tid >> 7); j < 64; j += 2) {
        float4 o = make_float4(0.f, 0.f, 0.f, 0.f);
#pragma unroll
        for (int r = 0; r < Rr; r++) {
            float c = c_s[j * 8 + r];
            o.x = fmaf(c, wv[r].x, o.x);
            o.y = fmaf(c, wv[r].y, o.y);
            o.z = fmaf(c, wv[r].z, o.z);
            o.w = fmaf(c, wv[r].w, o.w);
        }
        out4[((size_t)b * Ss + s0 + j) * (Dd / 4) + d4] = o;
    }
}

// ---------------------------------------------------------------------------
extern "C" void kernel_launch(void* const* d_in, const int* in_sizes, int n_in,
                              void* d_out, int out_size) {
    const float* src_emb  = (const float*)d_in[0];
    const float* tar_emb  = (const float*)d_in[1];
    const float* src_mask = (const float*)d_in[2];
    const float* tar_mask = (const float*)d_in[3];
    const float* w        = (const float*)d_in[4];
    float* out            = (float*)d_out;

    k_norm<<<1, 256>>>(w);
    k_dots<<<(Bb * Ss + Bb * Tt) / 8, 256>>>(src_emb, tar_emb);
    k_attn<<<Bb * Rr, 512>>>(src_mask, tar_mask);
    k_out<<<Bb * (Ss / 64), 256>>>(out);
}

// round 2
// speedup vs baseline: 1.2737x; 1.2737x over previous
#include <cuda_runtime.h>
#include <math.h>

#define Bb 16
#define Ss 512
#define Tt 512
#define Dd 512
#define Rr 8
#define NEG_BIG (-1e10f)
#define LOG2E 1.4426950408889634f

// scratch (device globals; no allocation allowed)
__device__ float g_wn[Rr * Dd];            // normalized w
__device__ float g_src_wt[Bb * Rr * Ss];   // [b,r,s]
__device__ float g_tar_wt[Bb * Rr * Tt];   // [b,r,t]
__device__ float g_c[Bb * Rr * Ss];        // softmax-weighted sum over t

__device__ __forceinline__ float ex2(float x) {
    float y;
    asm("ex2.approx.f32 %0, %1;" : "=f"(y) : "f"(x));
    return y;
}

// ---------------------------------------------------------------------------
// Kernel 1: row-L2-normalize w  (1 block, 8 warps, warp r handles row r)
// ---------------------------------------------------------------------------
__global__ void k_norm(const float* __restrict__ w) {
    int warp = threadIdx.x >> 5;
    int lane = threadIdx.x & 31;
    if (warp >= Rr) return;
    const float4* row = (const float4*)(w + warp * Dd);
    float4 x[4];
    float ss = 0.f;
#pragma unroll
    for (int k = 0; k < 4; k++) {
        x[k] = row[lane + 32 * k];
        ss += x[k].x * x[k].x + x[k].y * x[k].y + x[k].z * x[k].z + x[k].w * x[k].w;
    }
#pragma unroll
    for (int off = 16; off; off >>= 1)
        ss += __shfl_xor_sync(0xffffffffu, ss, off);
    float n = sqrtf(ss);
    float sc = 1.0f / fmaxf(n, 1e-12f);
    float4* outp = (float4*)(g_wn + warp * Dd);
#pragma unroll
    for (int k = 0; k < 4; k++) {
        float4 y;
        y.x = x[k].x * sc; y.y = x[k].y * sc; y.z = x[k].z * sc; y.w = x[k].w * sc;
        outp[lane + 32 * k] = y;
    }
}

// ---------------------------------------------------------------------------
// Kernel 2: src_wt[b,r,s] = src_emb[b,s,:]·wn[r,:], same for tar.
// One warp per row. 16 warps/block, 1024 blocks covers B*S + B*T = 16384 rows.
// ---------------------------------------------------------------------------
__global__ __launch_bounds__(512) void k_dots(const float* __restrict__ src,
                                              const float* __restrict__ tar) {
    __shared__ float4 wn_s[Rr * Dd / 4];  // 16 KB
    for (int i = threadIdx.x; i < Rr * Dd / 4; i += 512)
        wn_s[i] = ((const float4*)g_wn)[i];
    __syncthreads();

    int warp = threadIdx.x >> 5;
    int lane = threadIdx.x & 31;
    int gid = blockIdx.x * 16 + warp;

    const float4* row4;
    if (gid < Bb * Ss) row4 = (const float4*)(src + (size_t)gid * Dd);
    else               row4 = (const float4*)(tar + (size_t)(gid - Bb * Ss) * Dd);

    float acc[Rr];
#pragma unroll
    for (int r = 0; r < Rr; r++) acc[r] = 0.f;

#pragma unroll
    for (int k = 0; k < 4; k++) {
        float4 x = row4[lane + 32 * k];
#pragma unroll
        for (int r = 0; r < Rr; r++) {
            float4 wv = wn_s[r * 128 + lane + 32 * k];
            acc[r] = fmaf(x.x, wv.x, acc[r]);
            acc[r] = fmaf(x.y, wv.y, acc[r]);
            acc[r] = fmaf(x.z, wv.z, acc[r]);
            acc[r] = fmaf(x.w, wv.w, acc[r]);
        }
    }
#pragma unroll
    for (int off = 16; off; off >>= 1) {
#pragma unroll
        for (int r = 0; r < Rr; r++)
            acc[r] += __shfl_xor_sync(0xffffffffu, acc[r], off);
    }
    if (lane == 0) {
        float* dst;
        if (gid < Bb * Ss) {
            int b = gid / Ss, s = gid % Ss;
            dst = g_src_wt + (size_t)b * Rr * Ss + s;
        } else {
            int g2 = gid - Bb * Ss;
            int b = g2 / Tt, t = g2 % Tt;
            dst = g_tar_wt + (size_t)b * Rr * Tt + t;
        }
#pragma unroll
        for (int r = 0; r < Rr; r++) dst[r * Ss] = acc[r];  // S == T
    }
}

// ---------------------------------------------------------------------------
// Kernel 3: c[b,r,s] = sum_t softmax_t( a_s*v_t + (1 - sm_s*tm_t)*NEG_BIG ) * v_t
// grid = B*R blocks, 512 threads (one per s).
// Fast path (all tar_mask==1 && src_mask[s]==1): max is analytic (a*vmax or
// a*vmin, exact because fp-multiply by a scalar is monotone), single pass,
// 4 ALU ops + 1 MUFU per element. Slow path: general two-pass softmax.
// ---------------------------------------------------------------------------
__global__ __launch_bounds__(512) void k_attn(const float* __restrict__ src_mask,
                                              const float* __restrict__ tar_mask) {
    __shared__ float v_s[Tt];
    __shared__ float tm_s[Tt];
    __shared__ float red_max[16], red_min[16];
    __shared__ int   red_one[16];
    __shared__ float s_vmax, s_vmin;
    __shared__ int   s_allones;

    int b = blockIdx.x / Rr;
    int r = blockIdx.x % Rr;
    int s = threadIdx.x;

    if (s < 128)       ((float4*)v_s)[s]        = ((const float4*)(g_tar_wt + ((size_t)b * Rr + r) * Tt))[s];
    else if (s < 256)  ((float4*)tm_s)[s - 128] = ((const float4*)(tar_mask + (size_t)b * Tt))[s - 128];
    __syncthreads();

    // block reduce: vmax, vmin over all t; allones = all(tm==1)
    {
        float v = v_s[s], tm = tm_s[s];
        float cmax = v, cmin = v;
        int one = (tm == 1.0f);
#pragma unroll
        for (int off = 16; off; off >>= 1) {
            cmax = fmaxf(cmax, __shfl_xor_sync(0xffffffffu, cmax, off));
            cmin = fminf(cmin, __shfl_xor_sync(0xffffffffu, cmin, off));
            one &= __shfl_xor_sync(0xffffffffu, one, off);
        }
        int wid = s >> 5;
        if ((s & 31) == 0) { red_max[wid] = cmax; red_min[wid] = cmin; red_one[wid] = one; }
        __syncthreads();
        if (s < 16) {
            cmax = red_max[s]; cmin = red_min[s]; one = red_one[s];
#pragma unroll
            for (int off = 8; off; off >>= 1) {
                cmax = fmaxf(cmax, __shfl_xor_sync(0xffffu, cmax, off));
                cmin = fminf(cmin, __shfl_xor_sync(0xffffu, cmin, off));
                one &= __shfl_xor_sync(0xffffu, one, off);
            }
            if (s == 0) { s_vmax = cmax; s_vmin = cmin; s_allones = one; }
        }
        __syncthreads();
    }

    float a  = g_src_wt[((size_t)b * Rr + r) * Ss + s];
    float sm = src_mask[(size_t)b * Ss + s];
    float sum = 0.f, acc = 0.f;

    if (s_allones && sm == 1.0f) {
        // exact max of rounded products: multiply by scalar is monotone
        float m   = (a >= 0.f) ? a * s_vmax : a * s_vmin;
        float a2  = a * LOG2E;
        float nm2 = -m * LOG2E;
        const float4* vv = (const float4*)v_s;
#pragma unroll 4
        for (int t4 = 0; t4 < Tt / 4; t4++) {
            float4 v = vv[t4];
            float e0 = ex2(fmaf(a2, v.x, nm2));
            float e1 = ex2(fmaf(a2, v.y, nm2));
            float e2 = ex2(fmaf(a2, v.z, nm2));
            float e3 = ex2(fmaf(a2, v.w, nm2));
            sum += e0 + e1 + e2 + e3;
            acc = fmaf(e0, v.x, acc);
            acc = fmaf(e1, v.y, acc);
            acc = fmaf(e2, v.z, acc);
            acc = fmaf(e3, v.w, acc);
        }
    } else {
        // general two-pass
        const float4* vv = (const float4*)v_s;
        const float4* tt = (const float4*)tm_s;
        float m = -3.4e38f;
#pragma unroll 4
        for (int t4 = 0; t4 < Tt / 4; t4++) {
            float4 v = vv[t4], tm = tt[t4];
            float x0 = fmaf(a, v.x, fmaf(sm * tm.x, 1e10f, NEG_BIG));
            float x1 = fmaf(a, v.y, fmaf(sm * tm.y, 1e10f, NEG_BIG));
            float x2 = fmaf(a, v.z, fmaf(sm * tm.z, 1e10f, NEG_BIG));
            float x3 = fmaf(a, v.w, fmaf(sm * tm.w, 1e10f, NEG_BIG));
            m = fmaxf(m, fmaxf(fmaxf(x0, x1), fmaxf(x2, x3)));
        }
#pragma unroll 4
        for (int t4 = 0; t4 < Tt / 4; t4++) {
            float4 v = vv[t4], tm = tt[t4];
            float x0 = fmaf(a, v.x, fmaf(sm * tm.x, 1e10f, NEG_BIG));
            float x1 = fmaf(a, v.y, fmaf(sm * tm.y, 1e10f, NEG_BIG));
            float x2 = fmaf(a, v.z, fmaf(sm * tm.z, 1e10f, NEG_BIG));
            float x3 = fmaf(a, v.w, fmaf(sm * tm.w, 1e10f, NEG_BIG));
            float e0 = ex2((x0 - m) * LOG2E);
            float e1 = ex2((x1 - m) * LOG2E);
            float e2 = ex2((x2 - m) * LOG2E);
            float e3 = ex2((x3 - m) * LOG2E);
            sum += e0 + e1 + e2 + e3;
            acc = fmaf(e0, v.x, acc);
            acc = fmaf(e1, v.y, acc);
            acc = fmaf(e2, v.z, acc);
            acc = fmaf(e3, v.w, acc);
        }
    }
    g_c[((size_t)b * Rr + r) * Ss + s] = acc / sum;
}

// ---------------------------------------------------------------------------
// Kernel 4: out[b,s,d] = sum_r c[b,r,s] * wn[r,d]
// grid = B * (S/16) = 512 blocks, 256 threads. Thread owns a fixed d-float4,
// wn held in registers, 8 iterations over 16 s values (2 per pass).
// ---------------------------------------------------------------------------
__global__ __launch_bounds__(256) void k_out(float* __restrict__ out) {
    __shared__ float c_s[16 * Rr];  // [j][r]
    int b    = blockIdx.x >> 5;
    int s0   = (blockIdx.x & 31) * 16;
    int tid  = threadIdx.x;

    if (tid < 16 * Rr) {
        int j = tid >> 3, r = tid & 7;
        c_s[tid] = g_c[((size_t)b * Rr + r) * Ss + s0 + j];
    }
    __syncthreads();

    int d4   = tid & 127;
    int half = tid >> 7;
    float4 wv[Rr];
#pragma unroll
    for (int r = 0; r < Rr; r++) wv[r] = ((const float4*)g_wn)[r * 128 + d4];

    float4* out4 = (float4*)out;
#pragma unroll
    for (int k = 0; k < 8; k++) {
        int j = 2 * k + half;
        float4 o = make_float4(0.f, 0.f, 0.f, 0.f);
#pragma unroll
        for (int r = 0; r < Rr; r++) {
            float c = c_s[j * 8 + r];
            o.x = fmaf(c, wv[r].x, o.x);
            o.y = fmaf(c, wv[r].y, o.y);
            o.z = fmaf(c, wv[r].z, o.z);
            o.w = fmaf(c, wv[r].w, o.w);
        }
        out4[((size_t)b * Ss + s0 + j) * (Dd / 4) + d4] = o;
    }
}

// ---------------------------------------------------------------------------
extern "C" void kernel_launch(void* const* d_in, const int* in_sizes, int n_in,
                              void* d_out, int out_size) {
    const float* src_emb  = (const float*)d_in[0];
    const float* tar_emb  = (const float*)d_in[1];
    const float* src_mask = (const float*)d_in[2];
    const float* tar_mask = (const float*)d_in[3];
    const float* w        = (const float*)d_in[4];
    float* out            = (float*)d_out;

    k_norm<<<1, 256>>>(w);
    k_dots<<<(Bb * Ss + Bb * Tt) / 16, 512>>>(src_emb, tar_emb);
    k_attn<<<Bb * Rr, 512>>>(src_mask, tar_mask);
    k_out<<<Bb * (Ss / 16), 256>>>(out);
}

// round 3
// speedup vs baseline: 1.3389x; 1.0512x over previous
#include <cuda_runtime.h>
#include <math.h>

#define Bb 16
#define Ss 512
#define Tt 512
#define Dd 512
#define Rr 8
#define NEG_BIG (-1e10f)
#define LOG2E 1.4426950408889634f

// scratch (device globals; no allocation allowed)
__device__ float g_wn[Rr * Dd];            // normalized w (written by k_dots block 0)
__device__ float g_src_wt[Bb * Rr * Ss];   // [b,r,s]
__device__ float g_tar_wt[Bb * Rr * Tt];   // [b,r,t]

__device__ __forceinline__ float ex2(float x) {
    float y;
    asm("ex2.approx.f32 %0, %1;" : "=f"(y) : "f"(x));
    return y;
}

// ---------------------------------------------------------------------------
// Kernel 1: normalize w in-block, then src_wt[b,r,s] = src_emb[b,s,:]·wn[r,:]
// (same for tar). One warp per row, 16 warps/block, 1024 blocks cover
// B*S + B*T = 16384 rows. Block 0 also publishes g_wn for kernel 2.
// ---------------------------------------------------------------------------
__global__ __launch_bounds__(512) void k_dots(const float* __restrict__ src,
                                              const float* __restrict__ tar,
                                              const float* __restrict__ w) {
    __shared__ float4 wn_s[Rr * Dd / 4];  // 16 KB
    __shared__ float  sc_s[Rr];
    int tid  = threadIdx.x;
    int warp = tid >> 5;
    int lane = tid & 31;

    wn_s[tid]       = ((const float4*)w)[tid];
    wn_s[tid + 512] = ((const float4*)w)[tid + 512];
    __syncthreads();

    // row L2 norms: warp r reduces row r
    if (warp < Rr) {
        float ss = 0.f;
#pragma unroll
        for (int k = 0; k < 4; k++) {
            float4 x = wn_s[warp * 128 + lane + 32 * k];
            ss += x.x * x.x + x.y * x.y + x.z * x.z + x.w * x.w;
        }
#pragma unroll
        for (int off = 16; off; off >>= 1)
            ss += __shfl_xor_sync(0xffffffffu, ss, off);
        if (lane == 0) sc_s[warp] = 1.0f / fmaxf(sqrtf(ss), 1e-12f);
    }
    __syncthreads();

    // scale in place
    {
        float s0 = sc_s[tid >> 7];
        float s1 = sc_s[(tid + 512) >> 7];
        float4 v0 = wn_s[tid];
        float4 v1 = wn_s[tid + 512];
        v0.x *= s0; v0.y *= s0; v0.z *= s0; v0.w *= s0;
        v1.x *= s1; v1.y *= s1; v1.z *= s1; v1.w *= s1;
        wn_s[tid]       = v0;
        wn_s[tid + 512] = v1;
    }
    __syncthreads();

    if (blockIdx.x == 0) {
        ((float4*)g_wn)[tid]       = wn_s[tid];
        ((float4*)g_wn)[tid + 512] = wn_s[tid + 512];
    }

    // dot products: one warp per embedding row
    int gid = blockIdx.x * 16 + warp;
    const float4* row4;
    if (gid < Bb * Ss) row4 = (const float4*)(src + (size_t)gid * Dd);
    else               row4 = (const float4*)(tar + (size_t)(gid - Bb * Ss) * Dd);

    float acc[Rr];
#pragma unroll
    for (int r = 0; r < Rr; r++) acc[r] = 0.f;

#pragma unroll
    for (int k = 0; k < 4; k++) {
        float4 x = row4[lane + 32 * k];
#pragma unroll
        for (int r = 0; r < Rr; r++) {
            float4 wv = wn_s[r * 128 + lane + 32 * k];
            acc[r] = fmaf(x.x, wv.x, acc[r]);
            acc[r] = fmaf(x.y, wv.y, acc[r]);
            acc[r] = fmaf(x.z, wv.z, acc[r]);
            acc[r] = fmaf(x.w, wv.w, acc[r]);
        }
    }
#pragma unroll
    for (int off = 16; off; off >>= 1) {
#pragma unroll
        for (int r = 0; r < Rr; r++)
            acc[r] += __shfl_xor_sync(0xffffffffu, acc[r], off);
    }
    if (lane == 0) {
        float* dst;
        if (gid < Bb * Ss) {
            int b = gid / Ss, s = gid % Ss;
            dst = g_src_wt + (size_t)b * Rr * Ss + s;
        } else {
            int g2 = gid - Bb * Ss;
            int b = g2 / Tt, t = g2 % Tt;
            dst = g_tar_wt + (size_t)b * Rr * Tt + t;
        }
#pragma unroll
        for (int r = 0; r < Rr; r++) dst[r * Ss] = acc[r];  // S == T
    }
}

// ---------------------------------------------------------------------------
// Kernel 2 (fused attention + output):
// grid = B * (S/64) = 128 blocks, 512 threads.
// Phase A: thread (r = tid>>6, j = tid&63) computes
//   c[r][s0+j] = sum_t softmax_t( a*v_t + mask ) * v_t   (single pass,
//   analytic max when all masks == 1; general two-pass fallback).
// Phase B: out[b, s0+j, :] = sum_r c[r][j] * wn[r, :], wn in registers.
// ---------------------------------------------------------------------------
__global__ __launch_bounds__(512) void k_attn_out(const float* __restrict__ src_mask,
                                                  const float* __restrict__ tar_mask,
                                                  float* __restrict__ out) {
    __shared__ float v_s[Rr * Tt];    // 16 KB: tar_wt for all 8 r
    __shared__ float tm_s[Tt];
    __shared__ float a_s[Rr * 64];    // src_wt chunk [r][j]
    __shared__ float sm_s[64];
    __shared__ float c_s[64 * Rr];    // [j][r]
    __shared__ float red_max[Rr], red_min[Rr];
    __shared__ int   s_allones;

    int b   = blockIdx.x >> 3;
    int s0  = (blockIdx.x & 7) * 64;
    int tid = threadIdx.x;
    int warp = tid >> 5, lane = tid & 31;

    // loads: v for all r (4096 floats contiguous), masks, a chunk
    const float4* vsrc = (const float4*)(g_tar_wt + (size_t)b * Rr * Tt);
    ((float4*)v_s)[tid]       = vsrc[tid];
    ((float4*)v_s)[tid + 512] = vsrc[tid + 512];
    if (tid < 128) ((float4*)tm_s)[tid] = ((const float4*)(tar_mask + (size_t)b * Tt))[tid];
    {
        int r = tid >> 6, j = tid & 63;
        a_s[tid] = g_src_wt[((size_t)b * Rr + r) * Ss + s0 + j];
    }
    if (tid < 64) sm_s[tid] = src_mask[(size_t)b * Ss + s0 + tid];
    __syncthreads();

    // per-r vmax/vmin; warp 8 checks all-ones tar mask
    if (warp < Rr) {
        float cmax = -3.4e38f, cmin = 3.4e38f;
#pragma unroll
        for (int k = 0; k < 16; k++) {
            float v = v_s[warp * 512 + lane + 32 * k];
            cmax = fmaxf(cmax, v);
            cmin = fminf(cmin, v);
        }
#pragma unroll
        for (int off = 16; off; off >>= 1) {
            cmax = fmaxf(cmax, __shfl_xor_sync(0xffffffffu, cmax, off));
            cmin = fminf(cmin, __shfl_xor_sync(0xffffffffu, cmin, off));
        }
        if (lane == 0) { red_max[warp] = cmax; red_min[warp] = cmin; }
    } else if (warp == 8) {
        int one = 1;
#pragma unroll
        for (int k = 0; k < 16; k++)
            one &= (tm_s[lane + 32 * k] == 1.0f);
#pragma unroll
        for (int off = 16; off; off >>= 1)
            one &= __shfl_xor_sync(0xffffffffu, one, off);
        if (lane == 0) s_allones = one;
    }
    __syncthreads();

    // Phase A: softmax-weighted sum over t
    {
        int r = tid >> 6, j = tid & 63;
        float a  = a_s[tid];
        float sm = sm_s[j];
        float sum = 0.f, acc = 0.f;
        const float4* vv = (const float4*)(v_s + r * Tt);

        if (s_allones && sm == 1.0f) {
            // exact max of rounded products: scalar multiply is monotone
            float m   = (a >= 0.f) ? a * red_max[r] : a * red_min[r];
            float a2  = a * LOG2E;
            float nm2 = -m * LOG2E;
#pragma unroll 4
            for (int t4 = 0; t4 < Tt / 4; t4++) {
                float4 v = vv[t4];
                float e0 = ex2(fmaf(a2, v.x, nm2));
                float e1 = ex2(fmaf(a2, v.y, nm2));
                float e2 = ex2(fmaf(a2, v.z, nm2));
                float e3 = ex2(fmaf(a2, v.w, nm2));
                sum += e0 + e1 + e2 + e3;
                acc = fmaf(e0, v.x, acc);
                acc = fmaf(e1, v.y, acc);
                acc = fmaf(e2, v.z, acc);
                acc = fmaf(e3, v.w, acc);
            }
        } else {
            const float4* tt = (const float4*)tm_s;
            float m = -3.4e38f;
#pragma unroll 4
            for (int t4 = 0; t4 < Tt / 4; t4++) {
                float4 v = vv[t4], tm = tt[t4];
                float x0 = fmaf(a, v.x, fmaf(sm * tm.x, 1e10f, NEG_BIG));
                float x1 = fmaf(a, v.y, fmaf(sm * tm.y, 1e10f, NEG_BIG));
                float x2 = fmaf(a, v.z, fmaf(sm * tm.z, 1e10f, NEG_BIG));
                float x3 = fmaf(a, v.w, fmaf(sm * tm.w, 1e10f, NEG_BIG));
                m = fmaxf(m, fmaxf(fmaxf(x0, x1), fmaxf(x2, x3)));
            }
#pragma unroll 4
            for (int t4 = 0; t4 < Tt / 4; t4++) {
                float4 v = vv[t4], tm = tt[t4];
                float x0 = fmaf(a, v.x, fmaf(sm * tm.x, 1e10f, NEG_BIG));
                float x1 = fmaf(a, v.y, fmaf(sm * tm.y, 1e10f, NEG_BIG));
                float x2 = fmaf(a, v.z, fmaf(sm * tm.z, 1e10f, NEG_BIG));
                float x3 = fmaf(a, v.w, fmaf(sm * tm.w, 1e10f, NEG_BIG));
                float e0 = ex2((x0 - m) * LOG2E);
                float e1 = ex2((x1 - m) * LOG2E);
                float e2 = ex2((x2 - m) * LOG2E);
                float e3 = ex2((x3 - m) * LOG2E);
                sum += e0 + e1 + e2 + e3;
                acc = fmaf(e0, v.x, acc);
                acc = fmaf(e1, v.y, acc);
                acc = fmaf(e2, v.z, acc);
                acc = fmaf(e3, v.w, acc);
            }
        }
        c_s[j * Rr + r] = acc / sum;
    }
    __syncthreads();

    // Phase B: out tile [64 s][512 d] = c · wn
    {
        int d4 = tid & 127;
        int jg = tid >> 7;  // 0..3
        float4 wv[Rr];
#pragma unroll
        for (int r = 0; r < Rr; r++) wv[r] = ((const float4*)g_wn)[r * 128 + d4];

        float4* out4 = (float4*)out;
#pragma unroll
        for (int k = 0; k < 16; k++) {
            int j = jg + 4 * k;
            float4 o = make_float4(0.f, 0.f, 0.f, 0.f);
#pragma unroll
            for (int r = 0; r < Rr; r++) {
                float c = c_s[j * Rr + r];
                o.x = fmaf(c, wv[r].x, o.x);
                o.y = fmaf(c, wv[r].y, o.y);
                o.z = fmaf(c, wv[r].z, o.z);
                o.w = fmaf(c, wv[r].w, o.w);
            }
            out4[((size_t)b * Ss + s0 + j) * (Dd / 4) + d4] = o;
        }
    }
}

// ---------------------------------------------------------------------------
extern "C" void kernel_launch(void* const* d_in, const int* in_sizes, int n_in,
                              void* d_out, int out_size) {
    const float* src_emb  = (const float*)d_in[0];
    const float* tar_emb  = (const float*)d_in[1];
    const float* src_mask = (const float*)d_in[2];
    const float* tar_mask = (const float*)d_in[3];
    const float* w        = (const float*)d_in[4];
    float* out            = (float*)d_out;

    k_dots<<<(Bb * Ss + Bb * Tt) / 16, 512>>>(src_emb, tar_emb, w);
    k_attn_out<<<Bb * (Ss / 64), 512>>>(src_mask, tar_mask, out);
}

// round 4
// speedup vs baseline: 1.5549x; 1.1613x over previous
#include <cuda_runtime.h>
#include <math.h>

#define Bb 16
#define Ss 512
#define Tt 512
#define Dd 512
#define Rr 8
#define NEG_BIG (-1e10f)
#define LOG2E 1.4426950408889634f

// scratch (device globals; no allocation allowed)
__device__ float g_wn[Rr * Dd];            // normalized w (published by k_dots block 0)
__device__ float g_src_wt[Bb * Rr * Ss];   // [b,r,s]
__device__ float g_tar_wt[Bb * Rr * Tt];   // [b,r,t]

__device__ __forceinline__ float ex2(float x) {
    float y;
    asm("ex2.approx.f32 %0, %1;" : "=f"(y) : "f"(x));
    return y;
}

// ---------------------------------------------------------------------------
// Kernel 1: normalize w in smem, then dot each embedding row with all 8 wn rows.
// 256 threads (8 warps), each warp handles 4 consecutive rows so every w LDS
// is reused 4x (smem traffic /4). 512 blocks x 32 rows = 16384 rows.
// ---------------------------------------------------------------------------
__global__ __launch_bounds__(256) void k_dots(const float* __restrict__ src,
                                              const float* __restrict__ tar,
                                              const float* __restrict__ w) {
    __shared__ float4 wn_s[Rr * Dd / 4];  // 16 KB
    __shared__ float  sc_s[Rr];
    int tid  = threadIdx.x;
    int warp = tid >> 5;
    int lane = tid & 31;

#pragma unroll
    for (int i = 0; i < 4; i++)
        wn_s[tid + 256 * i] = ((const float4*)w)[tid + 256 * i];
    __syncthreads();

    // row L2 norms: warp r reduces row r
    if (warp < Rr) {
        float ss = 0.f;
#pragma unroll
        for (int k = 0; k < 4; k++) {
            float4 x = wn_s[warp * 128 + lane + 32 * k];
            ss += x.x * x.x + x.y * x.y + x.z * x.z + x.w * x.w;
        }
#pragma unroll
        for (int off = 16; off; off >>= 1)
            ss += __shfl_xor_sync(0xffffffffu, ss, off);
        if (lane == 0) sc_s[warp] = 1.0f / fmaxf(sqrtf(ss), 1e-12f);
    }
    __syncthreads();

#pragma unroll
    for (int i = 0; i < 4; i++) {
        int idx = tid + 256 * i;
        float s = sc_s[idx >> 7];
        float4 v = wn_s[idx];
        v.x *= s; v.y *= s; v.z *= s; v.w *= s;
        wn_s[idx] = v;
    }
    __syncthreads();

    if (blockIdx.x == 0) {
#pragma unroll
        for (int i = 0; i < 4; i++)
            ((float4*)g_wn)[tid + 256 * i] = wn_s[tid + 256 * i];
    }

    // 4 rows per warp
    int base = blockIdx.x * 32 + warp * 4;
    bool is_src = base < Bb * Ss;                 // blocks never straddle (8192 % 32 == 0)
    const float* eb = is_src ? src : tar;
    int lbase = is_src ? base : base - Bb * Ss;

    float4 x[4][4];
#pragma unroll
    for (int rr = 0; rr < 4; rr++) {
        const float4* rp = (const float4*)(eb + (size_t)(lbase + rr) * Dd);
#pragma unroll
        for (int k = 0; k < 4; k++) x[rr][k] = rp[lane + 32 * k];
    }

    float acc[4][Rr];
#pragma unroll
    for (int rr = 0; rr < 4; rr++)
#pragma unroll
        for (int r = 0; r < Rr; r++) acc[rr][r] = 0.f;

#pragma unroll
    for (int k = 0; k < 4; k++) {
#pragma unroll
        for (int r = 0; r < Rr; r++) {
            float4 wv = wn_s[r * 128 + lane + 32 * k];
#pragma unroll
            for (int rr = 0; rr < 4; rr++) {
                acc[rr][r] = fmaf(x[rr][k].x, wv.x, acc[rr][r]);
                acc[rr][r] = fmaf(x[rr][k].y, wv.y, acc[rr][r]);
                acc[rr][r] = fmaf(x[rr][k].z, wv.z, acc[rr][r]);
                acc[rr][r] = fmaf(x[rr][k].w, wv.w, acc[rr][r]);
            }
        }
    }

#pragma unroll
    for (int off = 16; off; off >>= 1)
#pragma unroll
        for (int rr = 0; rr < 4; rr++)
#pragma unroll
            for (int r = 0; r < Rr; r++)
                acc[rr][r] += __shfl_xor_sync(0xffffffffu, acc[rr][r], off);

    if (lane == 0) {
        float* gw = is_src ? g_src_wt : g_tar_wt;
#pragma unroll
        for (int rr = 0; rr < 4; rr++) {
            int gid = lbase + rr;
            int bb = gid >> 9, s = gid & 511;
#pragma unroll
            for (int r = 0; r < Rr; r++)
                gw[((size_t)bb * Rr + r) * Ss + s] = acc[rr][r];
        }
    }
}

// ---------------------------------------------------------------------------
// Kernel 2 (fused attention + output): grid = B*(S/32) = 256 blocks, 512 thr.
// Thread layout: half = tid>>8, r = (tid>>5)&7, j = tid&31 (s offset).
// Phase A: each thread accumulates sum/acc over its 256-t half; halves
// combined via smem. Fast path (all masks 1): analytic max (a*vmax / a*vmin,
// exact: scalar fp multiply is monotone), single pass. Slow path: two-pass.
// Branch is block-uniform (mask flags reduced in smem) so barriers align.
// Phase B: out tile [32 s][512 d] = c · wn with wn in registers.
// ---------------------------------------------------------------------------
__global__ __launch_bounds__(512) void k_attn_out(const float* __restrict__ src_mask,
                                                  const float* __restrict__ tar_mask,
                                                  float* __restrict__ out) {
    __shared__ float v_s[Rr * Tt];    // 16 KB
    __shared__ float tm_s[Tt];
    __shared__ float a_s[Rr * 32];
    __shared__ float sm_s[32];
    __shared__ float ps[512], pa[512], pm[512];
    __shared__ float c_s[32 * Rr];
    __shared__ float red_max[Rr], red_min[Rr];
    __shared__ int   s_tmok, s_smok;

    int b   = blockIdx.x >> 4;
    int s0  = (blockIdx.x & 15) * 32;
    int tid = threadIdx.x;
    int warp = tid >> 5, lane = tid & 31;
    int half = tid >> 8;          // 0/1: which 256-t range
    int r    = (tid >> 5) & 7;
    int j    = tid & 31;

    const float4* vsrc = (const float4*)(g_tar_wt + (size_t)b * Rr * Tt);
    ((float4*)v_s)[tid]       = vsrc[tid];
    ((float4*)v_s)[tid + 512] = vsrc[tid + 512];
    if (tid < 128) ((float4*)tm_s)[tid] = ((const float4*)(tar_mask + (size_t)b * Tt))[tid];
    if (tid < 256) a_s[tid] = g_src_wt[((size_t)b * Rr + (tid >> 5)) * Ss + s0 + (tid & 31)];
    if (tid < 32)  sm_s[tid] = src_mask[(size_t)b * Ss + s0 + tid];
    __syncthreads();

    // per-r vmax/vmin; warp 8: tar mask check; warp 9: src mask chunk check
    if (warp < Rr) {
        float cmax = -3.4e38f, cmin = 3.4e38f;
#pragma unroll
        for (int k = 0; k < 16; k++) {
            float v = v_s[warp * 512 + lane + 32 * k];
            cmax = fmaxf(cmax, v);
            cmin = fminf(cmin, v);
        }
#pragma unroll
        for (int off = 16; off; off >>= 1) {
            cmax = fmaxf(cmax, __shfl_xor_sync(0xffffffffu, cmax, off));
            cmin = fminf(cmin, __shfl_xor_sync(0xffffffffu, cmin, off));
        }
        if (lane == 0) { red_max[warp] = cmax; red_min[warp] = cmin; }
    } else if (warp == 8) {
        int one = 1;
#pragma unroll
        for (int k = 0; k < 16; k++)
            one &= (tm_s[lane + 32 * k] == 1.0f);
        one = (__ballot_sync(0xffffffffu, one) == 0xffffffffu);
        if (lane == 0) s_tmok = one;
    } else if (warp == 9) {
        int one = (sm_s[lane] == 1.0f);
        one = (__ballot_sync(0xffffffffu, one) == 0xffffffffu);
        if (lane == 0) s_smok = one;
    }
    __syncthreads();

    float a  = a_s[tid & 255];
    const float4* vv = (const float4*)(v_s + r * Tt) + half * 64;
    const float4* tt = (const float4*)tm_s + half * 64;
    float sum = 0.f, acc = 0.f;

    if (s_tmok && s_smok) {
        float m   = (a >= 0.f) ? a * red_max[r] : a * red_min[r];
        float a2  = a * LOG2E;
        float nm2 = -m * LOG2E;
#pragma unroll 4
        for (int t4 = 0; t4 < 64; t4++) {
            float4 v = vv[t4];
            float e0 = ex2(fmaf(a2, v.x, nm2));
            float e1 = ex2(fmaf(a2, v.y, nm2));
            float e2 = ex2(fmaf(a2, v.z, nm2));
            float e3 = ex2(fmaf(a2, v.w, nm2));
            sum += e0 + e1 + e2 + e3;
            acc = fmaf(e0, v.x, acc);
            acc = fmaf(e1, v.y, acc);
            acc = fmaf(e2, v.z, acc);
            acc = fmaf(e3, v.w, acc);
        }
        ps[tid] = sum; pa[tid] = acc;
        __syncthreads();
    } else {
        float sm = sm_s[j];
        float m = -3.4e38f;
#pragma unroll 4
        for (int t4 = 0; t4 < 64; t4++) {
            float4 v = vv[t4], tm = tt[t4];
            float x0 = fmaf(a, v.x, fmaf(sm * tm.x, 1e10f, NEG_BIG));
            float x1 = fmaf(a, v.y, fmaf(sm * tm.y, 1e10f, NEG_BIG));
            float x2 = fmaf(a, v.z, fmaf(sm * tm.z, 1e10f, NEG_BIG));
            float x3 = fmaf(a, v.w, fmaf(sm * tm.w, 1e10f, NEG_BIG));
            m = fmaxf(m, fmaxf(fmaxf(x0, x1), fmaxf(x2, x3)));
        }
        pm[tid] = m;
        __syncthreads();
        m = fmaxf(pm[tid], pm[tid ^ 256]);   // global max across both halves
#pragma unroll 4
        for (int t4 = 0; t4 < 64; t4++) {
            float4 v = vv[t4], tm = tt[t4];
            float x0 = fmaf(a, v.x, fmaf(sm * tm.x, 1e10f, NEG_BIG));
            float x1 = fmaf(a, v.y, fmaf(sm * tm.y, 1e10f, NEG_BIG));
            float x2 = fmaf(a, v.z, fmaf(sm * tm.z, 1e10f, NEG_BIG));
            float x3 = fmaf(a, v.w, fmaf(sm * tm.w, 1e10f, NEG_BIG));
            float e0 = ex2((x0 - m) * LOG2E);
            float e1 = ex2((x1 - m) * LOG2E);
            float e2 = ex2((x2 - m) * LOG2E);
            float e3 = ex2((x3 - m) * LOG2E);
            sum += e0 + e1 + e2 + e3;
            acc = fmaf(e0, v.x, acc);
            acc = fmaf(e1, v.y, acc);
            acc = fmaf(e2, v.z, acc);
            acc = fmaf(e3, v.w, acc);
        }
        ps[tid] = sum; pa[tid] = acc;
        __syncthreads();
    }

    if (tid < 256) {
        float S = ps[tid] + ps[tid + 256];
        float A = pa[tid] + pa[tid + 256];
        c_s[(tid & 31) * Rr + (tid >> 5)] = A / S;
    }
    __syncthreads();

    // Phase B: out tile [32 s][512 d] = c · wn
    {
        int d4 = tid & 127;
        int jg = tid >> 7;  // 0..3
        float4 wv[Rr];
#pragma unroll
        for (int rr = 0; rr < Rr; rr++) wv[rr] = ((const float4*)g_wn)[rr * 128 + d4];

        float4* out4 = (float4*)out;
#pragma unroll
        for (int k = 0; k < 8; k++) {
            int jj = jg + 4 * k;
            float4 o = make_float4(0.f, 0.f, 0.f, 0.f);
#pragma unroll
            for (int rr = 0; rr < Rr; rr++) {
                float c = c_s[jj * Rr + rr];
                o.x = fmaf(c, wv[rr].x, o.x);
                o.y = fmaf(c, wv[rr].y, o.y);
                o.z = fmaf(c, wv[rr].z, o.z);
                o.w = fmaf(c, wv[rr].w, o.w);
            }
            out4[((size_t)b * Ss + s0 + jj) * (Dd / 4) + d4] = o;
        }
    }
}

// ---------------------------------------------------------------------------
extern "C" void kernel_launch(void* const* d_in, const int* in_sizes, int n_in,
                              void* d_out, int out_size) {
    const float* src_emb  = (const float*)d_in[0];
    const float* tar_emb  = (const float*)d_in[1];
    const float* src_mask = (const float*)d_in[2];
    const float* tar_mask = (const float*)d_in[3];
    const float* w        = (const float*)d_in[4];
    float* out            = (float*)d_out;

    k_dots<<<(Bb * Ss + Bb * Tt) / 32, 256>>>(src_emb, tar_emb, w);
    k_attn_out<<<Bb * (Ss / 32), 512>>>(src_mask, tar_mask, out);
}

// round 5
// speedup vs baseline: 1.7356x; 1.1162x over previous
#include <cuda_runtime.h>
#include <cuda_fp16.h>
#include <math.h>

#define Bb 16
#define Ss 512
#define Tt 512
#define Dd 512
#define Rr 8
#define NEG_BIG (-1e10f)
#define LOG2E 1.4426950408889634f

typedef unsigned long long u64;

// scratch (device globals; no allocation allowed)
__device__ float g_wn[Rr * Dd];            // normalized w (published by k_dots block 0)
__device__ float g_src_wt[Bb * Rr * Ss];   // [b,r,s]
__device__ float g_tar_wt[Bb * Rr * Tt];   // [b,r,t]

__device__ __forceinline__ float ex2(float x) {
    float y;
    asm("ex2.approx.f32 %0, %1;" : "=f"(y) : "f"(x));
    return y;
}
__device__ __forceinline__ u64 pk(float lo, float hi) {
    u64 d; asm("mov.b64 %0, {%1, %2};" : "=l"(d) : "f"(lo), "f"(hi)); return d;
}
__device__ __forceinline__ void upk(u64 p, float& lo, float& hi) {
    asm("mov.b64 {%0, %1}, %2;" : "=f"(lo), "=f"(hi) : "l"(p));
}
__device__ __forceinline__ u64 ffma2(u64 a, u64 b, u64 c) {
    u64 d; asm("fma.rn.f32x2 %0, %1, %2, %3;" : "=l"(d) : "l"(a), "l"(b), "l"(c)); return d;
}
__device__ __forceinline__ u64 fadd2(u64 a, u64 b) {
    u64 d; asm("add.rn.f32x2 %0, %1, %2;" : "=l"(d) : "l"(a), "l"(b)); return d;
}
__device__ __forceinline__ unsigned ex2h2(unsigned x) {
    unsigned y; asm("ex2.approx.f16x2 %0, %1;" : "=r"(y) : "r"(x)); return y;
}

// ---------------------------------------------------------------------------
// Kernel 1: normalize w in smem, then dot each embedding row with all 8 wn rows.
// 256 threads (8 warps), 4 rows/warp, packed f32x2 FMAs, butterfly reduction
// landing acc-index == lane so each lane does exactly 1 store.
// ---------------------------------------------------------------------------
__global__ __launch_bounds__(256) void k_dots(const float* __restrict__ src,
                                              const float* __restrict__ tar,
                                              const float* __restrict__ w) {
    __shared__ float4 wn_s[Rr * Dd / 4];  // 16 KB
    __shared__ float  sc_s[Rr];
    int tid  = threadIdx.x;
    int warp = tid >> 5;
    int lane = tid & 31;

#pragma unroll
    for (int i = 0; i < 4; i++)
        wn_s[tid + 256 * i] = ((const float4*)w)[tid + 256 * i];
    __syncthreads();

    if (warp < Rr) {
        float ss = 0.f;
#pragma unroll
        for (int k = 0; k < 4; k++) {
            float4 x = wn_s[warp * 128 + lane + 32 * k];
            ss += x.x * x.x + x.y * x.y + x.z * x.z + x.w * x.w;
        }
#pragma unroll
        for (int off = 16; off; off >>= 1)
            ss += __shfl_xor_sync(0xffffffffu, ss, off);
        if (lane == 0) sc_s[warp] = 1.0f / fmaxf(sqrtf(ss), 1e-12f);
    }
    __syncthreads();

#pragma unroll
    for (int i = 0; i < 4; i++) {
        int idx = tid + 256 * i;
        float s = sc_s[idx >> 7];
        float4 v = wn_s[idx];
        v.x *= s; v.y *= s; v.z *= s; v.w *= s;
        wn_s[idx] = v;
    }
    __syncthreads();

    if (blockIdx.x == 0) {
#pragma unroll
        for (int i = 0; i < 4; i++)
            ((float4*)g_wn)[tid + 256 * i] = wn_s[tid + 256 * i];
    }

    int base = blockIdx.x * 32 + warp * 4;
    bool is_src = base < Bb * Ss;            // blocks never straddle (8192 % 32 == 0)
    const float* eb = is_src ? src : tar;
    int lbase = is_src ? base : base - Bb * Ss;

    u64 acc2[4][Rr];
#pragma unroll
    for (int rr = 0; rr < 4; rr++)
#pragma unroll
        for (int r = 0; r < Rr; r++) acc2[rr][r] = 0ull;

#pragma unroll
    for (int k = 0; k < 4; k++) {
        u64 xp01[4], xp23[4];
#pragma unroll
        for (int rr = 0; rr < 4; rr++) {
            float4 x = ((const float4*)(eb + (size_t)(lbase + rr) * Dd))[lane + 32 * k];
            xp01[rr] = pk(x.x, x.y);
            xp23[rr] = pk(x.z, x.w);
        }
#pragma unroll
        for (int r = 0; r < Rr; r++) {
            float4 wv = wn_s[r * 128 + lane + 32 * k];
            u64 w01 = pk(wv.x, wv.y);
            u64 w23 = pk(wv.z, wv.w);
#pragma unroll
            for (int rr = 0; rr < 4; rr++) {
                acc2[rr][r] = ffma2(xp01[rr], w01, acc2[rr][r]);
                acc2[rr][r] = ffma2(xp23[rr], w23, acc2[rr][r]);
            }
        }
    }

    // fold even/odd lanes, then butterfly: final t[0] at lane L = acc index L
    float t[32];
#pragma unroll
    for (int rr = 0; rr < 4; rr++)
#pragma unroll
        for (int r = 0; r < Rr; r++) {
            float lo, hi;
            upk(acc2[rr][r], lo, hi);
            t[rr * 8 + r] = lo + hi;
        }

#pragma unroll
    for (int st = 0; st < 5; st++) {
        int off = 1 << st;
        int sel = lane & off;
#pragma unroll
        for (int j = 0; j < (16 >> st); j++) {
            float give = sel ? t[2 * j]     : t[2 * j + 1];
            float keep = sel ? t[2 * j + 1] : t[2 * j];
            float recv = __shfl_xor_sync(0xffffffffu, give, off);
            t[j] = keep + recv;
        }
    }

    {
        int rr = lane >> 3, r = lane & 7;
        int gid = lbase + rr;
        int bb = gid >> 9, s = gid & 511;
        float* gw = is_src ? g_src_wt : g_tar_wt;
        gw[((size_t)bb * Rr + r) * Ss + s] = t[0];
    }
}

// ---------------------------------------------------------------------------
// Kernel 2 (fused attention + output): grid = B*(S/32) = 256 blocks, 512 thr.
// half = tid>>8, r = (tid>>5)&7, j = tid&31. Fast path: analytic max +
// f16x2 exp (2 exps / MUFU op) with packed-f32x2 score & accumulation.
// Slow path: general two-pass fp32 (block-uniform branch).
// Phase B: out tile [32 s][512 d] = c · wn with wn in registers.
// ---------------------------------------------------------------------------
__global__ __launch_bounds__(512) void k_attn_out(const float* __restrict__ src_mask,
                                                  const float* __restrict__ tar_mask,
                                                  float* __restrict__ out) {
    __shared__ float v_s[Rr * Tt];    // 16 KB
    __shared__ float tm_s[Tt];
    __shared__ float a_s[Rr * 32];
    __shared__ float sm_s[32];
    __shared__ float ps[512], pa[512], pm[512];
    __shared__ float c_s[32 * Rr];
    __shared__ float red_max[Rr], red_min[Rr];
    __shared__ int   s_tmok, s_smok;

    int b   = blockIdx.x >> 4;
    int s0  = (blockIdx.x & 15) * 32;
    int tid = threadIdx.x;
    int warp = tid >> 5, lane = tid & 31;
    int half = tid >> 8;
    int r    = (tid >> 5) & 7;
    int j    = tid & 31;

    const float4* vsrc = (const float4*)(g_tar_wt + (size_t)b * Rr * Tt);
    ((float4*)v_s)[tid]       = vsrc[tid];
    ((float4*)v_s)[tid + 512] = vsrc[tid + 512];
    if (tid < 128) ((float4*)tm_s)[tid] = ((const float4*)(tar_mask + (size_t)b * Tt))[tid];
    if (tid < 256) a_s[tid] = g_src_wt[((size_t)b * Rr + (tid >> 5)) * Ss + s0 + (tid & 31)];
    if (tid < 32)  sm_s[tid] = src_mask[(size_t)b * Ss + s0 + tid];
    __syncthreads();

    if (warp < Rr) {
        float cmax = -3.4e38f, cmin = 3.4e38f;
#pragma unroll
        for (int k = 0; k < 16; k++) {
            float v = v_s[warp * 512 + lane + 32 * k];
            cmax = fmaxf(cmax, v);
            cmin = fminf(cmin, v);
        }
#pragma unroll
        for (int off = 16; off; off >>= 1) {
            cmax = fmaxf(cmax, __shfl_xor_sync(0xffffffffu, cmax, off));
            cmin = fminf(cmin, __shfl_xor_sync(0xffffffffu, cmin, off));
        }
        if (lane == 0) { red_max[warp] = cmax; red_min[warp] = cmin; }
    } else if (warp == 8) {
        int one = 1;
#pragma unroll
        for (int k = 0; k < 16; k++)
            one &= (tm_s[lane + 32 * k] == 1.0f);
        one = (__ballot_sync(0xffffffffu, one) == 0xffffffffu);
        if (lane == 0) s_tmok = one;
    } else if (warp == 9) {
        int one = (sm_s[lane] == 1.0f);
        one = (__ballot_sync(0xffffffffu, one) == 0xffffffffu);
        if (lane == 0) s_smok = one;
    }
    __syncthreads();

    float a  = a_s[tid & 255];
    const float4* vv = (const float4*)(v_s + r * Tt) + half * 64;
    const float4* tt = (const float4*)tm_s + half * 64;

    if (s_tmok && s_smok) {
        float m   = (a >= 0.f) ? a * red_max[r] : a * red_min[r];
        float a2  = a * LOG2E;
        float nm2 = -m * LOG2E;
        u64 a2p  = pk(a2, a2);
        u64 nm2p = pk(nm2, nm2);
        u64 sum2a = 0ull, sum2b = 0ull, acc2a = 0ull, acc2b = 0ull;
#pragma unroll 4
        for (int t4 = 0; t4 < 64; t4++) {
            float4 v = vv[t4];
            u64 v01 = pk(v.x, v.y);
            u64 v23 = pk(v.z, v.w);
            u64 x01 = ffma2(a2p, v01, nm2p);
            u64 x23 = ffma2(a2p, v23, nm2p);
            float x0, x1, x2, x3;
            upk(x01, x0, x1);
            upk(x23, x2, x3);
            __half2 h01 = __floats2half2_rn(x0, x1);
            __half2 h23 = __floats2half2_rn(x2, x3);
            unsigned u01 = ex2h2(*reinterpret_cast<unsigned*>(&h01));
            unsigned u23 = ex2h2(*reinterpret_cast<unsigned*>(&h23));
            float2 e01 = __half22float2(*reinterpret_cast<__half2*>(&u01));
            float2 e23 = __half22float2(*reinterpret_cast<__half2*>(&u23));
            u64 e01p = pk(e01.x, e01.y);
            u64 e23p = pk(e23.x, e23.y);
            sum2a = fadd2(sum2a, e01p);
            sum2b = fadd2(sum2b, e23p);
            acc2a = ffma2(e01p, v01, acc2a);
            acc2b = ffma2(e23p, v23, acc2b);
        }
        float sl, sh, al, ah, bl, bh;
        upk(fadd2(sum2a, sum2b), sl, sh);
        upk(acc2a, al, ah);
        upk(acc2b, bl, bh);
        ps[tid] = sl + sh;
        pa[tid] = (al + ah) + (bl + bh);
        __syncthreads();
    } else {
        float sm = sm_s[j];
        float sum = 0.f, acc = 0.f;
        float m = -3.4e38f;
#pragma unroll 4
        for (int t4 = 0; t4 < 64; t4++) {
            float4 v = vv[t4], tm = tt[t4];
            float x0 = fmaf(a, v.x, fmaf(sm * tm.x, 1e10f, NEG_BIG));
            float x1 = fmaf(a, v.y, fmaf(sm * tm.y, 1e10f, NEG_BIG));
            float x2 = fmaf(a, v.z, fmaf(sm * tm.z, 1e10f, NEG_BIG));
            float x3 = fmaf(a, v.w, fmaf(sm * tm.w, 1e10f, NEG_BIG));
            m = fmaxf(m, fmaxf(fmaxf(x0, x1), fmaxf(x2, x3)));
        }
        pm[tid] = m;
        __syncthreads();
        m = fmaxf(pm[tid], pm[tid ^ 256]);
#pragma unroll 4
        for (int t4 = 0; t4 < 64; t4++) {
            float4 v = vv[t4], tm = tt[t4];
            float x0 = fmaf(a, v.x, fmaf(sm * tm.x, 1e10f, NEG_BIG));
            float x1 = fmaf(a, v.y, fmaf(sm * tm.y, 1e10f, NEG_BIG));
            float x2 = fmaf(a, v.z, fmaf(sm * tm.z, 1e10f, NEG_BIG));
            float x3 = fmaf(a, v.w, fmaf(sm * tm.w, 1e10f, NEG_BIG));
            float e0 = ex2((x0 - m) * LOG2E);
            float e1 = ex2((x1 - m) * LOG2E);
            float e2 = ex2((x2 - m) * LOG2E);
            float e3 = ex2((x3 - m) * LOG2E);
            sum += e0 + e1 + e2 + e3;
            acc = fmaf(e0, v.x, acc);
            acc = fmaf(e1, v.y, acc);
            acc = fmaf(e2, v.z, acc);
            acc = fmaf(e3, v.w, acc);
        }
        ps[tid] = sum; pa[tid] = acc;
        __syncthreads();
    }

    if (tid < 256) {
        float S = ps[tid] + ps[tid + 256];
        float A = pa[tid] + pa[tid + 256];
        c_s[(tid & 31) * Rr + (tid >> 5)] = A / S;
    }
    __syncthreads();

    // Phase B: out tile [32 s][512 d] = c · wn
    {
        int d4 = tid & 127;
        int jg = tid >> 7;
        float4 wv[Rr];
#pragma unroll
        for (int rr = 0; rr < Rr; rr++) wv[rr] = ((const float4*)g_wn)[rr * 128 + d4];

        float4* out4 = (float4*)out;
#pragma unroll
        for (int k = 0; k < 8; k++) {
            int jj = jg + 4 * k;
            float4 o = make_float4(0.f, 0.f, 0.f, 0.f);
#pragma unroll
            for (int rr = 0; rr < Rr; rr++) {
                float c = c_s[jj * Rr + rr];
                o.x = fmaf(c, wv[rr].x, o.x);
                o.y = fmaf(c, wv[rr].y, o.y);
                o.z = fmaf(c, wv[rr].z, o.z);
                o.w = fmaf(c, wv[rr].w, o.w);
            }
            out4[((size_t)b * Ss + s0 + jj) * (Dd / 4) + d4] = o;
        }
    }
}

// ---------------------------------------------------------------------------
extern "C" void kernel_launch(void* const* d_in, const int* in_sizes, int n_in,
                              void* d_out, int out_size) {
    const float* src_emb  = (const float*)d_in[0];
    const float* tar_emb  = (const float*)d_in[1];
    const float* src_mask = (const float*)d_in[2];
    const float* tar_mask = (const float*)d_in[3];
    const float* w        = (const float*)d_in[4];
    float* out            = (float*)d_out;

    k_dots<<<(Bb * Ss + Bb * Tt) / 32, 256>>>(src_emb, tar_emb, w);
    k_attn_out<<<Bb * (Ss / 32), 512>>>(src_mask, tar_mask, out);
}